// round 16
// baseline (speedup 1.0000x reference)
#include <cuda_runtime.h>
#include <cuda_bf16.h>
#include <math.h>
#include <limits.h>

// Problem constants
#define NB    4
#define LL    4096
#define DD    1024
#define HH    16
#define EE    64
#define BB    64          // NB*HH
#define CC    256
#define BITS  32
#define KM_ITERS 10
#define MM    16384       // NB*LL
#define TEMP_F 0.125f

// ---------------- scratch (__device__ globals; no allocation allowed) ----------------
__device__ float    g_q[(size_t)BB * LL * EE];
__device__ float    g_k[(size_t)BB * LL * EE];
__device__ float    g_v[(size_t)BB * LL * EE];
__device__ unsigned g_codes[BB * LL];
__device__ unsigned g_cent[BB * CC];
__device__ int      g_histc[BB * CC];
__device__ unsigned g_histb[BB * CC * 16];
__device__ int      g_assign[BB * LL];
__device__ int      g_cnt[BB * CC];
__device__ float    g_qc[(size_t)BB * CC * EE];
__device__ float    g_vc[(size_t)BB * CC * EE];

// ---------------- tf32 split helpers ----------------
__device__ __forceinline__ void split_tf32(float x, unsigned &hi, unsigned &lo)
{
    unsigned h;
    asm("cvt.rna.tf32.f32 %0, %1;" : "=r"(h) : "f"(x));
    float l = x - __uint_as_float(h);
    unsigned l32;
    asm("cvt.rna.tf32.f32 %0, %1;" : "=r"(l32) : "f"(l));
    hi = h; lo = l32;
}
__device__ __forceinline__ void split_tf32f(float x, float &hi, float &lo)
{
    unsigned h, l;
    split_tf32(x, h, l);
    hi = __uint_as_float(h); lo = __uint_as_float(l);
}

__device__ __forceinline__ void mma_tf32(float c[4],
                                         unsigned a0, unsigned a1, unsigned a2, unsigned a3,
                                         unsigned b0, unsigned b1)
{
    asm volatile(
        "mma.sync.aligned.m16n8k8.row.col.f32.tf32.tf32.f32 "
        "{%0,%1,%2,%3}, {%4,%5,%6,%7}, {%8,%9}, {%0,%1,%2,%3};\n"
        : "+f"(c[0]), "+f"(c[1]), "+f"(c[2]), "+f"(c[3])
        : "r"(a0), "r"(a1), "r"(a2), "r"(a3), "r"(b0), "r"(b1));
}
__device__ __forceinline__ void mma_tf32f(float c[4],
                                          float a0, float a1, float a2, float a3,
                                          float b0, float b1)
{
    mma_tf32(c, __float_as_uint(a0), __float_as_uint(a1),
                __float_as_uint(a2), __float_as_uint(a3),
                __float_as_uint(b0), __float_as_uint(b1));
}

// =============== EXACT q GEMM body (FROZEN ARITHMETIC — Eigen gebp, KC=248 panels) ===============
// Register-staged prefetch (bench-verified bit-exact in round 11).
__device__ __forceinline__ void gemm_q_body(const float* __restrict__ A,
                                            const float* __restrict__ W,
                                            const float* __restrict__ bias,
                                            int by, int bx,
                                            float (*As)[68], float (*Ws)[132])
{
    const int K = 1024, N = 1024;
    const int Mrow = by * 64;
    const int Ncol = bx * 128;
    const int tid = threadIdx.x;
    const int tx = tid % 16, ty = tid / 16;
    const int arow = tid / 4;
    const int acol = (tid % 4) * 8;
    const int wrow = tid / 32;
    const int wcol = (tid % 32) * 4;

    float c_[4][8], t_[4][8];
#pragma unroll
    for (int i = 0; i < 4; i++)
#pragma unroll
        for (int j = 0; j < 8; j++) { c_[i][j] = 0.f; t_[i][j] = 0.f; }

    float4 ra0, ra1, rw[4];
    {
        const float* ap = &A[(size_t)(Mrow + arow) * K + acol];
        ra0 = *(const float4*)&ap[0];
        ra1 = *(const float4*)&ap[4];
#pragma unroll
        for (int r = 0; r < 4; r++)
            rw[r] = *(const float4*)&W[(size_t)(wrow + r * 8) * N + Ncol + wcol];
    }

    for (int kt = 0; kt < K; kt += 32) {
        As[acol + 0][arow] = ra0.x; As[acol + 1][arow] = ra0.y;
        As[acol + 2][arow] = ra0.z; As[acol + 3][arow] = ra0.w;
        As[acol + 4][arow] = ra1.x; As[acol + 5][arow] = ra1.y;
        As[acol + 6][arow] = ra1.z; As[acol + 7][arow] = ra1.w;
#pragma unroll
        for (int r = 0; r < 4; r++)
            *(float4*)&Ws[wrow + r * 8][wcol] = rw[r];
        __syncthreads();
        if (kt + 32 < K) {
            const float* ap = &A[(size_t)(Mrow + arow) * K + kt + 32 + acol];
            ra0 = *(const float4*)&ap[0];
            ra1 = *(const float4*)&ap[4];
#pragma unroll
            for (int r = 0; r < 4; r++)
                rw[r] = *(const float4*)&W[(size_t)(kt + 32 + wrow + r * 8) * N + Ncol + wcol];
        }
#pragma unroll
        for (int g = 0; g < 4; g++) {
#pragma unroll
            for (int kk8 = 0; kk8 < 8; kk8++) {
                const int kk = g * 8 + kk8;
                float4 av = *(const float4*)&As[kk][ty * 4];
                float4 b0 = *(const float4*)&Ws[kk][tx * 8];
                float4 b1 = *(const float4*)&Ws[kk][tx * 8 + 4];
                float a[4] = {av.x, av.y, av.z, av.w};
                float b[8] = {b0.x, b0.y, b0.z, b0.w, b1.x, b1.y, b1.z, b1.w};
#pragma unroll
                for (int i = 0; i < 4; i++)
#pragma unroll
                    for (int j = 0; j < 8; j++)
                        t_[i][j] = fmaf(a[i], b[j], t_[i][j]);
            }
            const int kend = kt + g * 8 + 8;
            if (kend == 248 || kend == 496 || kend == 744 || kend == 992 || kend == 1024) {
#pragma unroll
                for (int i = 0; i < 4; i++)
#pragma unroll
                    for (int j = 0; j < 8; j++) {
                        c_[i][j] = __fadd_rn(c_[i][j], t_[i][j]);
                        t_[i][j] = 0.f;
                    }
            }
        }
        __syncthreads();
    }
#pragma unroll
    for (int i = 0; i < 4; i++) {
        int m = Mrow + ty * 4 + i;
#pragma unroll
        for (int j = 0; j < 8; j++) {
            int col = Ncol + tx * 8 + j;
            float val = c_[i][j] + bias[col];
            int n = m >> 12, l = m & 4095, h = col >> 6, e = col & 63;
            g_q[(((size_t)(n * 16 + h)) * 4096 + l) * 64 + e] = val;
        }
    }
}

// =============== 3xTF32 tensor-core GEMM body with register prefetch ===============
// MODE 0: A from global, output remapped to [b][l][e]  (k/v projections)
// MODE 1: A gathered from g_vc via g_assign, plain row-major output (out GEMM)
template<int MODE>
__device__ __forceinline__ void tf32_gemm_body(const float* __restrict__ A,
                                               const float* __restrict__ W,
                                               const float* __restrict__ bias,
                                               float* __restrict__ out,
                                               int by, int bx,
                                               float (*As)[136], float (*Ws)[132])
{
    const int K = 1024, N = 1024;
    const int Mrow = by * 128;
    const int Ncol = bx * 128;
    const int tid = threadIdx.x;
    const int warp = tid >> 5, lane = tid & 31;
    const int grp = lane >> 2, tig = lane & 3;
    const int wm = (warp & 3) * 32;
    const int wn = (warp >> 2) * 64;
    const int ar = tid >> 2;
    const int akc = (tid & 3) * 4;
    const int wkr = tid >> 5;
    const int wnc = (tid & 31) * 4;

    float acc[2][8][4];
#pragma unroll
    for (int tm = 0; tm < 2; tm++)
#pragma unroll
        for (int tn = 0; tn < 8; tn++)
#pragma unroll
            for (int r = 0; r < 4; r++) acc[tm][tn][r] = 0.f;

    // prefetch helpers
    float4 pa[2], pw[2];
    auto load_tile = [&](int kt) {
#pragma unroll
        for (int i = 0; i < 2; i++) {
            const int m = Mrow + ar + i * 64;
            if (MODE == 1) {
                const int col = kt + akc;
                const int n_ = m >> 12, l = m & 4095;
                const int h = col >> 6, e4 = col & 63;
                const int b = n_ * 16 + h;
                const int c = g_assign[b * LL + l];
                pa[i] = *(const float4*)&g_vc[((size_t)(b * CC + c)) * 64 + e4];
            } else {
                pa[i] = *(const float4*)&A[(size_t)m * K + kt + akc];
            }
            pw[i] = *(const float4*)&W[(size_t)(kt + wkr + i * 8) * N + Ncol + wnc];
        }
    };
    load_tile(0);

    for (int kt = 0; kt < K; kt += 16) {
#pragma unroll
        for (int i = 0; i < 2; i++) {
            As[akc + 0][ar + i * 64] = pa[i].x;
            As[akc + 1][ar + i * 64] = pa[i].y;
            As[akc + 2][ar + i * 64] = pa[i].z;
            As[akc + 3][ar + i * 64] = pa[i].w;
            *(float4*)&Ws[wkr + i * 8][wnc] = pw[i];
        }
        __syncthreads();
        if (kt + 16 < K) load_tile(kt + 16);
#pragma unroll
        for (int ks = 0; ks < 2; ks++) {
            const int k0 = ks * 8;
            unsigned ah[2][4], al[2][4];
#pragma unroll
            for (int tm = 0; tm < 2; tm++) {
                split_tf32(As[k0 + tig    ][wm + tm * 16 + grp    ], ah[tm][0], al[tm][0]);
                split_tf32(As[k0 + tig    ][wm + tm * 16 + grp + 8], ah[tm][1], al[tm][1]);
                split_tf32(As[k0 + tig + 4][wm + tm * 16 + grp    ], ah[tm][2], al[tm][2]);
                split_tf32(As[k0 + tig + 4][wm + tm * 16 + grp + 8], ah[tm][3], al[tm][3]);
            }
#pragma unroll
            for (int tn = 0; tn < 8; tn++) {
                unsigned bh0, bl0, bh1, bl1;
                split_tf32(Ws[k0 + tig    ][wn + tn * 8 + grp], bh0, bl0);
                split_tf32(Ws[k0 + tig + 4][wn + tn * 8 + grp], bh1, bl1);
#pragma unroll
                for (int tm = 0; tm < 2; tm++) {
                    mma_tf32(acc[tm][tn], ah[tm][0], ah[tm][1], ah[tm][2], ah[tm][3], bh0, bh1);
                    mma_tf32(acc[tm][tn], ah[tm][0], ah[tm][1], ah[tm][2], ah[tm][3], bl0, bl1);
                    mma_tf32(acc[tm][tn], al[tm][0], al[tm][1], al[tm][2], al[tm][3], bh0, bh1);
                }
            }
        }
        __syncthreads();
    }
#pragma unroll
    for (int tm = 0; tm < 2; tm++) {
#pragma unroll
        for (int tn = 0; tn < 8; tn++) {
#pragma unroll
            for (int r = 0; r < 2; r++) {
                const int m = Mrow + wm + tm * 16 + grp + r * 8;
                const int n = Ncol + wn + tn * 8 + tig * 2;
                const float v0 = acc[tm][tn][r * 2 + 0] + bias[n];
                const float v1 = acc[tm][tn][r * 2 + 1] + bias[n + 1];
                if (MODE == 0) {
                    const int nb = m >> 12, l = m & 4095;
                    const int h = n >> 6, e = n & 63;
                    float* p = &out[(((size_t)(nb * 16 + h)) * 4096 + l) * 64 + e];
                    p[0] = v0; p[1] = v1;
                } else {
                    out[(size_t)m * 1024 + n] = v0;
                    out[(size_t)m * 1024 + n + 1] = v1;
                }
            }
        }
    }
}

// =============== MERGED qkv kernel (round-14 structure) ===============
__global__ void __launch_bounds__(256) gemm_qkv_mixed(const float* __restrict__ x,
                                                      const float* __restrict__ Wq,
                                                      const float* __restrict__ bq,
                                                      const float* __restrict__ Wk,
                                                      const float* __restrict__ bk,
                                                      const float* __restrict__ Wv,
                                                      const float* __restrict__ bv)
{
    __shared__ __align__(16) char smem_raw[32 * 68 * 4 + 32 * 132 * 4];
    const int kind = blockIdx.x & 1;
    const int xt = blockIdx.x >> 1;
    const int y = blockIdx.y;
    if (kind == 0) {
        float (*As)[68]  = (float(*)[68])smem_raw;
        float (*Ws)[132] = (float(*)[132])(smem_raw + 32 * 68 * 4);
        gemm_q_body(x, Wq, bq, y, xt, As, Ws);
    } else {
        float (*As)[136] = (float(*)[136])smem_raw;
        float (*Ws)[132] = (float(*)[132])(smem_raw + 16 * 136 * 4);
        const int sel = y >> 7;
        const int my = y & 127;
        if (sel == 0) tf32_gemm_body<0>(x, Wk, bk, g_k, my, xt, As, Ws);
        else          tf32_gemm_body<0>(x, Wv, bv, g_v, my, xt, As, Ws);
    }
}

// =============== output GEMM with fused gather ===============
__global__ void __launch_bounds__(256) gemm_out_g(const float* __restrict__ W,
                                                  const float* __restrict__ bias,
                                                  float* __restrict__ out)
{
    __shared__ __align__(16) char smem_raw[16 * 136 * 4 + 16 * 132 * 4];
    float (*As)[136] = (float(*)[136])smem_raw;
    float (*Ws)[132] = (float(*)[132])(smem_raw + 16 * 136 * 4);
    tf32_gemm_body<1>(nullptr, W, bias, out, blockIdx.y, blockIdx.x, As, Ws);
}

// ---------------- codes = pack(q @ planes > 0)  (FROZEN) ----------------
__global__ void __launch_bounds__(256) codes_kernel(const float* __restrict__ planes)
{
    __shared__ float pl[64 * 32];
    const int tid = threadIdx.x;
    for (int i = tid; i < 2048; i += 256) pl[i] = planes[i];
    __syncthreads();
    const int warp = tid / 32, lane = tid % 32;
    const int rowBase = (blockIdx.x * 8 + warp) * 16;
    for (int r = 0; r < 16; r++) {
        const int row = rowBase + r;
        const float* qrow = &g_q[(size_t)row * 64];
        float s = 0.f;
#pragma unroll
        for (int e = 0; e < 64; e++)
            s = fmaf(__ldg(&qrow[e]), pl[e * 32 + lane], s);
        unsigned w = __ballot_sync(0xffffffffu, s > 0.f);
        if (lane == 0) g_codes[row] = w;
    }
}

// ---------------- k-means: init / assign / update (integer-exact) ----------------
__global__ void km_init()
{
    const int b = blockIdx.x, c = threadIdx.x;
    g_cent[b * CC + c] = g_codes[b * LL + (273 * c) / 17];
    g_histc[b * CC + c] = 0;
    g_cnt[b * CC + c] = 0;
#pragma unroll
    for (int j = 0; j < 16; j++) g_histb[(b * CC + c) * 16 + j] = 0;
}

// grid (16, 64): ONE point per thread (256 pts/block).
__global__ void __launch_bounds__(256) km_assign(int final_pass)
{
    __shared__ unsigned scent[CC];
    __shared__ int shc[CC];
    __shared__ unsigned shb[CC * 16];
    const int b = blockIdx.y;
    const int tid = threadIdx.x;
    scent[tid] = g_cent[b * CC + tid];
    if (!final_pass) {
        shc[tid] = 0;
        for (int i = tid; i < CC * 16; i += 256) shb[i] = 0;
    }
    __syncthreads();
    const int p = blockIdx.x * 256 + tid;
    {
        const unsigned w = g_codes[b * LL + p];
        int best = INT_MAX;
#pragma unroll 16
        for (int c = 0; c < CC; c++) {
            int d = __popc(w ^ scent[c]);
            best = min(best, (d << 8) | c);
        }
        const int bc = best & 255;
        if (final_pass) {
            g_assign[b * LL + p] = bc;
            atomicAdd(&g_cnt[b * CC + bc], 1);
        } else {
            atomicAdd(&shc[bc], 1);
#pragma unroll
            for (int j = 0; j < 16; j++) {
                unsigned contrib = ((w >> (2 * j)) & 1u) | (((w >> (2 * j + 1)) & 1u) << 16);
                if (contrib) atomicAdd(&shb[bc * 16 + j], contrib);
            }
        }
    }
    if (!final_pass) {
        __syncthreads();
        if (shc[tid]) atomicAdd(&g_histc[b * CC + tid], shc[tid]);
        for (int i = tid; i < CC * 16; i += 256) {
            unsigned v = shb[i];
            if (v) atomicAdd(&g_histb[b * CC * 16 + i], v);
        }
    }
}

__global__ void km_update()
{
    const int b = blockIdx.x, c = threadIdx.x;
    const int cnt = g_histc[b * CC + c];
    const unsigned old = g_cent[b * CC + c];
    unsigned nw = 0;
#pragma unroll
    for (int j = 0; j < 16; j++) {
        const unsigned pk = g_histb[(b * CC + c) * 16 + j];
        const int s0 = (int)(pk & 0xffffu);
        const int s1 = (int)(pk >> 16);
        if (2 * s0 >= cnt) nw |= 1u << (2 * j);
        if (2 * s1 >= cnt) nw |= 1u << (2 * j + 1);
        g_histb[(b * CC + c) * 16 + j] = 0;
    }
    g_cent[b * CC + c] = (cnt > 0) ? nw : old;
    g_histc[b * CC + c] = 0;
}

// ---------------- qc = segmented mean of q per cluster (FROZEN) ----------------
__global__ void __launch_bounds__(256) qc_kernel()
{
    __shared__ long long sq[CC * 17];
    const int b = blockIdx.y;
    const int eq = blockIdx.x * 16;
    const int tid = threadIdx.x;
    for (int i = tid; i < CC * 17; i += 256) sq[i] = 0;
    __syncthreads();
    for (int p = tid; p < LL; p += 256) {
        const int c = g_assign[b * LL + p];
        const float* q = &g_q[((size_t)(b * LL + p)) * 64 + eq];
#pragma unroll
        for (int e = 0; e < 16; e++) {
            long long v = (long long)llrintf(q[e] * 1073741824.0f);
            atomicAdd((unsigned long long*)&sq[c * 17 + e], (unsigned long long)v);
        }
    }
    __syncthreads();
    for (int i = tid; i < CC * 16; i += 256) {
        const int c = i / 16, e = i % 16;
        const float cnt = fmaxf((float)g_cnt[b * CC + c], 1.f);
        const double s = (double)sq[c * 17 + e] * (1.0 / 1073741824.0);
        g_qc[((size_t)(b * CC + c)) * 64 + eq + e] = (float)(s / (double)cnt);
    }
}

// ---------------- tensor-core fused attention (round-14 code) ----------------
__global__ void __launch_bounds__(256) attn_tc()
{
    __shared__ float qch[64][36], qcl[64][36];
    __shared__ float kvh[32][68], kvl[32][68];
    __shared__ float psh[32][36], psl[32][36];
    __shared__ float lsum[32];
    const int b = blockIdx.y;
    const int c0 = blockIdx.x * 32;
    const int tid = threadIdx.x;
    const int warp = tid >> 5, lane = tid & 31;
    const int grp = lane >> 2, tig = lane & 3;

    const int wms = (warp & 1) * 16;
    const int wnc = (warp >> 1) * 8;
    const int wmc = (warp & 1) * 16;
    const int wne = (warp >> 1) * 16;

    for (int i = tid; i < 32 * 16; i += 256) {
        const int c = i / 16, e4 = (i % 16) * 4;
        float4 v = *(const float4*)&g_qc[((size_t)(b * CC + c0 + c)) * 64 + e4];
        float h, l;
        split_tf32f(v.x, h, l); qch[e4 + 0][c] = h; qcl[e4 + 0][c] = l;
        split_tf32f(v.y, h, l); qch[e4 + 1][c] = h; qcl[e4 + 1][c] = l;
        split_tf32f(v.z, h, l); qch[e4 + 2][c] = h; qcl[e4 + 2][c] = l;
        split_tf32f(v.w, h, l); qch[e4 + 3][c] = h; qcl[e4 + 3][c] = l;
    }
    if (tid < 32) lsum[tid] = 0.f;

    float vacc[2][4];
#pragma unroll
    for (int tn = 0; tn < 2; tn++)
#pragma unroll
        for (int r = 0; r < 4; r++) vacc[tn][r] = 0.f;
    __syncthreads();

    for (int s0 = 0; s0 < LL; s0 += 32) {
        for (int i = tid; i < 32 * 16; i += 256) {
            const int s = i / 16, e4 = (i % 16) * 4;
            float4 v = *(const float4*)&g_k[((size_t)(b * LL + s0 + s)) * 64 + e4];
            float4 hv, lv;
            split_tf32f(v.x, hv.x, lv.x);
            split_tf32f(v.y, hv.y, lv.y);
            split_tf32f(v.z, hv.z, lv.z);
            split_tf32f(v.w, hv.w, lv.w);
            *(float4*)&kvh[s][e4] = hv;
            *(float4*)&kvl[s][e4] = lv;
        }
        __syncthreads();
        float sacc[4] = {0.f, 0.f, 0.f, 0.f};
#pragma unroll
        for (int k0 = 0; k0 < 64; k0 += 8) {
            float ah0 = kvh[wms + grp    ][k0 + tig    ];
            float ah1 = kvh[wms + grp + 8][k0 + tig    ];
            float ah2 = kvh[wms + grp    ][k0 + tig + 4];
            float ah3 = kvh[wms + grp + 8][k0 + tig + 4];
            float al0 = kvl[wms + grp    ][k0 + tig    ];
            float al1 = kvl[wms + grp + 8][k0 + tig    ];
            float al2 = kvl[wms + grp    ][k0 + tig + 4];
            float al3 = kvl[wms + grp + 8][k0 + tig + 4];
            float bh0 = qch[k0 + tig    ][wnc + grp];
            float bh1 = qch[k0 + tig + 4][wnc + grp];
            float bl0 = qcl[k0 + tig    ][wnc + grp];
            float bl1 = qcl[k0 + tig + 4][wnc + grp];
            mma_tf32f(sacc, ah0, ah1, ah2, ah3, bh0, bh1);
            mma_tf32f(sacc, ah0, ah1, ah2, ah3, bl0, bl1);
            mma_tf32f(sacc, al0, al1, al2, al3, bh0, bh1);
        }
#pragma unroll
        for (int r = 0; r < 2; r++)
#pragma unroll
            for (int j = 0; j < 2; j++) {
                const int srow = wms + grp + r * 8;
                const int ccol = wnc + tig * 2 + j;
                float ex = __expf(sacc[r * 2 + j] * TEMP_F);
                float h, l;
                split_tf32f(ex, h, l);
                psh[srow][ccol] = h;
                psl[srow][ccol] = l;
            }
        __syncthreads();
        for (int i = tid; i < 32 * 16; i += 256) {
            const int s = i / 16, e4 = (i % 16) * 4;
            float4 v = *(const float4*)&g_v[((size_t)(b * LL + s0 + s)) * 64 + e4];
            float4 hv, lv;
            split_tf32f(v.x, hv.x, lv.x);
            split_tf32f(v.y, hv.y, lv.y);
            split_tf32f(v.z, hv.z, lv.z);
            split_tf32f(v.w, hv.w, lv.w);
            *(float4*)&kvh[s][e4] = hv;
            *(float4*)&kvl[s][e4] = lv;
        }
        if (tid < 32) {
            float l = 0.f;
            for (int s = 0; s < 32; s++) l += psh[s][tid] + psl[s][tid];
            lsum[tid] += l;
        }
        __syncthreads();
#pragma unroll
        for (int k0 = 0; k0 < 32; k0 += 8) {
            float ah0 = psh[k0 + tig    ][wmc + grp    ];
            float ah1 = psh[k0 + tig    ][wmc + grp + 8];
            float ah2 = psh[k0 + tig + 4][wmc + grp    ];
            float ah3 = psh[k0 + tig + 4][wmc + grp + 8];
            float al0 = psl[k0 + tig    ][wmc + grp    ];
            float al1 = psl[k0 + tig    ][wmc + grp + 8];
            float al2 = psl[k0 + tig + 4][wmc + grp    ];
            float al3 = psl[k0 + tig + 4][wmc + grp + 8];
#pragma unroll
            for (int tn = 0; tn < 2; tn++) {
                const int n0 = wne + tn * 8 + grp;
                float bh0 = kvh[k0 + tig    ][n0];
                float bh1 = kvh[k0 + tig + 4][n0];
                float bl0 = kvl[k0 + tig    ][n0];
                float bl1 = kvl[k0 + tig + 4][n0];
                mma_tf32f(vacc[tn], ah0, ah1, ah2, ah3, bh0, bh1);
                mma_tf32f(vacc[tn], ah0, ah1, ah2, ah3, bl0, bl1);
                mma_tf32f(vacc[tn], al0, al1, al2, al3, bh0, bh1);
            }
        }
        __syncthreads();
    }
#pragma unroll
    for (int tn = 0; tn < 2; tn++)
#pragma unroll
        for (int r = 0; r < 2; r++) {
            const int cloc = wmc + grp + r * 8;
            const float inv = 1.f / lsum[cloc];
#pragma unroll
            for (int j = 0; j < 2; j++) {
                const int e = wne + tn * 8 + tig * 2 + j;
                g_vc[((size_t)(b * CC + c0 + cloc)) * 64 + e] = vacc[tn][r * 2 + j] * inv;
            }
        }
}

// ---------------- launch ----------------
extern "C" void kernel_launch(void* const* d_in, const int* in_sizes, int n_in,
                              void* d_out, int out_size)
{
    const float* x      = (const float*)d_in[0];
    const float* Wq     = (const float*)d_in[2];
    const float* bq     = (const float*)d_in[3];
    const float* Wk     = (const float*)d_in[4];
    const float* bk     = (const float*)d_in[5];
    const float* Wv     = (const float*)d_in[6];
    const float* bv     = (const float*)d_in[7];
    const float* Wo     = (const float*)d_in[8];
    const float* bo     = (const float*)d_in[9];
    const float* planes = (const float*)d_in[10];
    float* out = (float*)d_out;

    gemm_qkv_mixed<<<dim3(16, 256), 256>>>(x, Wq, bq, Wk, bk, Wv, bv);
    codes_kernel<<<2048, 256>>>(planes);                                // FROZEN
    km_init<<<64, 256>>>();
    for (int it = 0; it < KM_ITERS; it++) {
        km_assign<<<dim3(16, 64), 256>>>(0);
        km_update<<<64, 256>>>();
    }
    km_assign<<<dim3(16, 64), 256>>>(1);
    qc_kernel<<<dim3(4, 64), 256>>>();                                  // FROZEN
    attn_tc<<<dim3(8, 64), 256>>>();                                    // tensor-core attention
    gemm_out_g<<<dim3(8, 128), 256>>>(Wo, bo, out);
}

// round 17
// speedup vs baseline: 1.1036x; 1.1036x over previous
#include <cuda_runtime.h>
#include <cuda_bf16.h>
#include <math.h>
#include <limits.h>

// Problem constants
#define NB    4
#define LL    4096
#define DD    1024
#define HH    16
#define EE    64
#define BB    64          // NB*HH
#define CC    256
#define BITS  32
#define KM_ITERS 10
#define MM    16384       // NB*LL
#define TEMP_F 0.125f

// ---------------- scratch (__device__ globals; no allocation allowed) ----------------
__device__ float    g_q[(size_t)BB * LL * EE];
__device__ float    g_k[(size_t)BB * LL * EE];
__device__ float    g_v[(size_t)BB * LL * EE];
__device__ unsigned g_codes[BB * LL];
__device__ unsigned g_cent[BB * CC];
__device__ int      g_histc[BB * CC];
__device__ unsigned g_histb[BB * CC * 16];
__device__ int      g_assign[BB * LL];
__device__ int      g_cnt[BB * CC];
__device__ float    g_qc[(size_t)BB * CC * EE];
__device__ float    g_vc[(size_t)BB * CC * EE];

// ---------------- tf32 split helpers ----------------
__device__ __forceinline__ void split_tf32(float x, unsigned &hi, unsigned &lo)
{
    unsigned h;
    asm("cvt.rna.tf32.f32 %0, %1;" : "=r"(h) : "f"(x));
    float l = x - __uint_as_float(h);
    unsigned l32;
    asm("cvt.rna.tf32.f32 %0, %1;" : "=r"(l32) : "f"(l));
    hi = h; lo = l32;
}
__device__ __forceinline__ void split_tf32f(float x, float &hi, float &lo)
{
    unsigned h, l;
    split_tf32(x, h, l);
    hi = __uint_as_float(h); lo = __uint_as_float(l);
}

__device__ __forceinline__ void mma_tf32(float c[4],
                                         unsigned a0, unsigned a1, unsigned a2, unsigned a3,
                                         unsigned b0, unsigned b1)
{
    asm volatile(
        "mma.sync.aligned.m16n8k8.row.col.f32.tf32.tf32.f32 "
        "{%0,%1,%2,%3}, {%4,%5,%6,%7}, {%8,%9}, {%0,%1,%2,%3};\n"
        : "+f"(c[0]), "+f"(c[1]), "+f"(c[2]), "+f"(c[3])
        : "r"(a0), "r"(a1), "r"(a2), "r"(a3), "r"(b0), "r"(b1));
}
__device__ __forceinline__ void mma_tf32f(float c[4],
                                          float a0, float a1, float a2, float a3,
                                          float b0, float b1)
{
    mma_tf32(c, __float_as_uint(a0), __float_as_uint(a1),
                __float_as_uint(a2), __float_as_uint(a3),
                __float_as_uint(b0), __float_as_uint(b1));
}

// =============== EXACT q GEMM body (FROZEN — Eigen gebp, KC=248 panels; round-14 code) ===============
__device__ __forceinline__ void gemm_q_body(const float* __restrict__ A,
                                            const float* __restrict__ W,
                                            const float* __restrict__ bias,
                                            int by, int bx,
                                            float (*As)[68], float (*Ws)[132])
{
    const int K = 1024, N = 1024;
    const int Mrow = by * 64;
    const int Ncol = bx * 128;
    const int tid = threadIdx.x;
    const int tx = tid % 16, ty = tid / 16;
    const int arow = tid / 4;
    const int acol = (tid % 4) * 8;
    const int wrow = tid / 32;
    const int wcol = (tid % 32) * 4;

    float c_[4][8], t_[4][8];
#pragma unroll
    for (int i = 0; i < 4; i++)
#pragma unroll
        for (int j = 0; j < 8; j++) { c_[i][j] = 0.f; t_[i][j] = 0.f; }

    for (int kt = 0; kt < K; kt += 32) {
        {
            const float* arow_p = &A[(size_t)(Mrow + arow) * K + kt + acol];
            float4 a0 = *(const float4*)&arow_p[0];
            float4 a1 = *(const float4*)&arow_p[4];
            As[acol + 0][arow] = a0.x; As[acol + 1][arow] = a0.y;
            As[acol + 2][arow] = a0.z; As[acol + 3][arow] = a0.w;
            As[acol + 4][arow] = a1.x; As[acol + 5][arow] = a1.y;
            As[acol + 6][arow] = a1.z; As[acol + 7][arow] = a1.w;
        }
#pragma unroll
        for (int r = 0; r < 4; r++) {
            float4 wv = *(const float4*)&W[(size_t)(kt + wrow + r * 8) * N + Ncol + wcol];
            *(float4*)&Ws[wrow + r * 8][wcol] = wv;
        }
        __syncthreads();
#pragma unroll
        for (int g = 0; g < 4; g++) {
#pragma unroll
            for (int kk8 = 0; kk8 < 8; kk8++) {
                const int kk = g * 8 + kk8;
                float4 av = *(const float4*)&As[kk][ty * 4];
                float4 b0 = *(const float4*)&Ws[kk][tx * 8];
                float4 b1 = *(const float4*)&Ws[kk][tx * 8 + 4];
                float a[4] = {av.x, av.y, av.z, av.w};
                float b[8] = {b0.x, b0.y, b0.z, b0.w, b1.x, b1.y, b1.z, b1.w};
#pragma unroll
                for (int i = 0; i < 4; i++)
#pragma unroll
                    for (int j = 0; j < 8; j++)
                        t_[i][j] = fmaf(a[i], b[j], t_[i][j]);
            }
            const int kend = kt + g * 8 + 8;
            if (kend == 248 || kend == 496 || kend == 744 || kend == 992 || kend == 1024) {
#pragma unroll
                for (int i = 0; i < 4; i++)
#pragma unroll
                    for (int j = 0; j < 8; j++) {
                        c_[i][j] = __fadd_rn(c_[i][j], t_[i][j]);
                        t_[i][j] = 0.f;
                    }
            }
        }
        __syncthreads();
    }
#pragma unroll
    for (int i = 0; i < 4; i++) {
        int m = Mrow + ty * 4 + i;
#pragma unroll
        for (int j = 0; j < 8; j++) {
            int col = Ncol + tx * 8 + j;
            float val = c_[i][j] + bias[col];
            int n = m >> 12, l = m & 4095, h = col >> 6, e = col & 63;
            g_q[(((size_t)(n * 16 + h)) * 4096 + l) * 64 + e] = val;
        }
    }
}

// =============== 3xTF32 tensor-core GEMM body (round-14 code: split at fragment, no prefetch) ===============
template<int MODE>
__device__ __forceinline__ void tf32_gemm_body(const float* __restrict__ A,
                                               const float* __restrict__ W,
                                               const float* __restrict__ bias,
                                               float* __restrict__ out,
                                               int by, int bx,
                                               float (*As)[136], float (*Ws)[132])
{
    const int K = 1024, N = 1024;
    const int Mrow = by * 128;
    const int Ncol = bx * 128;
    const int tid = threadIdx.x;
    const int warp = tid >> 5, lane = tid & 31;
    const int grp = lane >> 2, tig = lane & 3;
    const int wm = (warp & 3) * 32;
    const int wn = (warp >> 2) * 64;

    float acc[2][8][4];
#pragma unroll
    for (int tm = 0; tm < 2; tm++)
#pragma unroll
        for (int tn = 0; tn < 8; tn++)
#pragma unroll
            for (int r = 0; r < 4; r++) acc[tm][tn][r] = 0.f;

    for (int kt = 0; kt < K; kt += 16) {
        {
            const int r = tid >> 2;
            const int kc = (tid & 3) * 4;
#pragma unroll
            for (int i = 0; i < 2; i++) {
                const int m = Mrow + r + i * 64;
                float4 av;
                if (MODE == 1) {
                    const int col = kt + kc;
                    const int n_ = m >> 12, l = m & 4095;
                    const int h = col >> 6, e4 = col & 63;
                    const int b = n_ * 16 + h;
                    const int c = g_assign[b * LL + l];
                    av = *(const float4*)&g_vc[((size_t)(b * CC + c)) * 64 + e4];
                } else {
                    av = *(const float4*)&A[(size_t)m * K + kt + kc];
                }
                As[kc + 0][r + i * 64] = av.x;
                As[kc + 1][r + i * 64] = av.y;
                As[kc + 2][r + i * 64] = av.z;
                As[kc + 3][r + i * 64] = av.w;
            }
        }
        {
            const int kr = tid >> 5;
            const int nc = (tid & 31) * 4;
#pragma unroll
            for (int i = 0; i < 2; i++) {
                float4 wv = *(const float4*)&W[(size_t)(kt + kr + i * 8) * N + Ncol + nc];
                *(float4*)&Ws[kr + i * 8][nc] = wv;
            }
        }
        __syncthreads();
#pragma unroll
        for (int ks = 0; ks < 2; ks++) {
            const int k0 = ks * 8;
            unsigned ah[2][4], al[2][4];
#pragma unroll
            for (int tm = 0; tm < 2; tm++) {
                split_tf32(As[k0 + tig    ][wm + tm * 16 + grp    ], ah[tm][0], al[tm][0]);
                split_tf32(As[k0 + tig    ][wm + tm * 16 + grp + 8], ah[tm][1], al[tm][1]);
                split_tf32(As[k0 + tig + 4][wm + tm * 16 + grp    ], ah[tm][2], al[tm][2]);
                split_tf32(As[k0 + tig + 4][wm + tm * 16 + grp + 8], ah[tm][3], al[tm][3]);
            }
#pragma unroll
            for (int tn = 0; tn < 8; tn++) {
                unsigned bh0, bl0, bh1, bl1;
                split_tf32(Ws[k0 + tig    ][wn + tn * 8 + grp], bh0, bl0);
                split_tf32(Ws[k0 + tig + 4][wn + tn * 8 + grp], bh1, bl1);
#pragma unroll
                for (int tm = 0; tm < 2; tm++) {
                    mma_tf32(acc[tm][tn], ah[tm][0], ah[tm][1], ah[tm][2], ah[tm][3], bh0, bh1);
                    mma_tf32(acc[tm][tn], ah[tm][0], ah[tm][1], ah[tm][2], ah[tm][3], bl0, bl1);
                    mma_tf32(acc[tm][tn], al[tm][0], al[tm][1], al[tm][2], al[tm][3], bh0, bh1);
                }
            }
        }
        __syncthreads();
    }
#pragma unroll
    for (int tm = 0; tm < 2; tm++) {
#pragma unroll
        for (int tn = 0; tn < 8; tn++) {
#pragma unroll
            for (int r = 0; r < 2; r++) {
                const int m = Mrow + wm + tm * 16 + grp + r * 8;
                const int n = Ncol + wn + tn * 8 + tig * 2;
                const float v0 = acc[tm][tn][r * 2 + 0] + bias[n];
                const float v1 = acc[tm][tn][r * 2 + 1] + bias[n + 1];
                if (MODE == 0) {
                    const int nb = m >> 12, l = m & 4095;
                    const int h = n >> 6, e = n & 63;
                    float* p = &out[(((size_t)(nb * 16 + h)) * 4096 + l) * 64 + e];
                    p[0] = v0; p[1] = v1;
                } else {
                    out[(size_t)m * 1024 + n] = v0;
                    out[(size_t)m * 1024 + n + 1] = v1;
                }
            }
        }
    }
}

// =============== MERGED qkv kernel (round-14 structure) ===============
__global__ void __launch_bounds__(256) gemm_qkv_mixed(const float* __restrict__ x,
                                                      const float* __restrict__ Wq,
                                                      const float* __restrict__ bq,
                                                      const float* __restrict__ Wk,
                                                      const float* __restrict__ bk,
                                                      const float* __restrict__ Wv,
                                                      const float* __restrict__ bv)
{
    __shared__ __align__(16) char smem_raw[32 * 68 * 4 + 32 * 132 * 4];
    const int kind = blockIdx.x & 1;
    const int xt = blockIdx.x >> 1;
    const int y = blockIdx.y;
    if (kind == 0) {
        float (*As)[68]  = (float(*)[68])smem_raw;
        float (*Ws)[132] = (float(*)[132])(smem_raw + 32 * 68 * 4);
        gemm_q_body(x, Wq, bq, y, xt, As, Ws);
    } else {
        float (*As)[136] = (float(*)[136])smem_raw;
        float (*Ws)[132] = (float(*)[132])(smem_raw + 16 * 136 * 4);
        const int sel = y >> 7;
        const int my = y & 127;
        if (sel == 0) tf32_gemm_body<0>(x, Wk, bk, g_k, my, xt, As, Ws);
        else          tf32_gemm_body<0>(x, Wv, bv, g_v, my, xt, As, Ws);
    }
}

// =============== output GEMM with fused gather ===============
__global__ void __launch_bounds__(256) gemm_out_g(const float* __restrict__ W,
                                                  const float* __restrict__ bias,
                                                  float* __restrict__ out)
{
    __shared__ __align__(16) char smem_raw[16 * 136 * 4 + 16 * 132 * 4];
    float (*As)[136] = (float(*)[136])smem_raw;
    float (*Ws)[132] = (float(*)[132])(smem_raw + 16 * 136 * 4);
    tf32_gemm_body<1>(nullptr, W, bias, out, blockIdx.y, blockIdx.x, As, Ws);
}

// ---------------- codes = pack(q @ planes > 0)  (FROZEN) ----------------
__global__ void __launch_bounds__(256) codes_kernel(const float* __restrict__ planes)
{
    __shared__ float pl[64 * 32];
    const int tid = threadIdx.x;
    for (int i = tid; i < 2048; i += 256) pl[i] = planes[i];
    __syncthreads();
    const int warp = tid / 32, lane = tid % 32;
    const int rowBase = (blockIdx.x * 8 + warp) * 16;
    for (int r = 0; r < 16; r++) {
        const int row = rowBase + r;
        const float* qrow = &g_q[(size_t)row * 64];
        float s = 0.f;
#pragma unroll
        for (int e = 0; e < 64; e++)
            s = fmaf(__ldg(&qrow[e]), pl[e * 32 + lane], s);
        unsigned w = __ballot_sync(0xffffffffu, s > 0.f);
        if (lane == 0) g_codes[row] = w;
    }
}

// ---------------- k-means: init / assign / update (integer-exact) ----------------
__global__ void km_init()
{
    const int b = blockIdx.x, c = threadIdx.x;
    g_cent[b * CC + c] = g_codes[b * LL + (273 * c) / 17];
    g_histc[b * CC + c] = 0;
    g_cnt[b * CC + c] = 0;
#pragma unroll
    for (int j = 0; j < 16; j++) g_histb[(b * CC + c) * 16 + j] = 0;
}

// grid (16, 64): ONE point per thread (measured faster than 2 pts/thread in round 16).
__global__ void __launch_bounds__(256) km_assign(int final_pass)
{
    __shared__ unsigned scent[CC];
    __shared__ int shc[CC];
    __shared__ unsigned shb[CC * 16];
    const int b = blockIdx.y;
    const int tid = threadIdx.x;
    scent[tid] = g_cent[b * CC + tid];
    if (!final_pass) {
        shc[tid] = 0;
        for (int i = tid; i < CC * 16; i += 256) shb[i] = 0;
    }
    __syncthreads();
    const int p = blockIdx.x * 256 + tid;
    {
        const unsigned w = g_codes[b * LL + p];
        int best = INT_MAX;
#pragma unroll 16
        for (int c = 0; c < CC; c++) {
            int d = __popc(w ^ scent[c]);
            best = min(best, (d << 8) | c);
        }
        const int bc = best & 255;
        if (final_pass) {
            g_assign[b * LL + p] = bc;
            atomicAdd(&g_cnt[b * CC + bc], 1);
        } else {
            atomicAdd(&shc[bc], 1);
#pragma unroll
            for (int j = 0; j < 16; j++) {
                unsigned contrib = ((w >> (2 * j)) & 1u) | (((w >> (2 * j + 1)) & 1u) << 16);
                if (contrib) atomicAdd(&shb[bc * 16 + j], contrib);
            }
        }
    }
    if (!final_pass) {
        __syncthreads();
        if (shc[tid]) atomicAdd(&g_histc[b * CC + tid], shc[tid]);
        for (int i = tid; i < CC * 16; i += 256) {
            unsigned v = shb[i];
            if (v) atomicAdd(&g_histb[b * CC * 16 + i], v);
        }
    }
}

__global__ void km_update()
{
    const int b = blockIdx.x, c = threadIdx.x;
    const int cnt = g_histc[b * CC + c];
    const unsigned old = g_cent[b * CC + c];
    unsigned nw = 0;
#pragma unroll
    for (int j = 0; j < 16; j++) {
        const unsigned pk = g_histb[(b * CC + c) * 16 + j];
        const int s0 = (int)(pk & 0xffffu);
        const int s1 = (int)(pk >> 16);
        if (2 * s0 >= cnt) nw |= 1u << (2 * j);
        if (2 * s1 >= cnt) nw |= 1u << (2 * j + 1);
        g_histb[(b * CC + c) * 16 + j] = 0;
    }
    g_cent[b * CC + c] = (cnt > 0) ? nw : old;
    g_histc[b * CC + c] = 0;
}

// ---------------- qc = segmented mean of q per cluster (FROZEN) ----------------
__global__ void __launch_bounds__(256) qc_kernel()
{
    __shared__ long long sq[CC * 17];
    const int b = blockIdx.y;
    const int eq = blockIdx.x * 16;
    const int tid = threadIdx.x;
    for (int i = tid; i < CC * 17; i += 256) sq[i] = 0;
    __syncthreads();
    for (int p = tid; p < LL; p += 256) {
        const int c = g_assign[b * LL + p];
        const float* q = &g_q[((size_t)(b * LL + p)) * 64 + eq];
#pragma unroll
        for (int e = 0; e < 16; e++) {
            long long v = (long long)llrintf(q[e] * 1073741824.0f);
            atomicAdd((unsigned long long*)&sq[c * 17 + e], (unsigned long long)v);
        }
    }
    __syncthreads();
    for (int i = tid; i < CC * 16; i += 256) {
        const int c = i / 16, e = i % 16;
        const float cnt = fmaxf((float)g_cnt[b * CC + c], 1.f);
        const double s = (double)sq[c * 17 + e] * (1.0 / 1073741824.0);
        g_qc[((size_t)(b * CC + c)) * 64 + eq + e] = (float)(s / (double)cnt);
    }
}

// ---------------- tensor-core fused attention (round-14 code) ----------------
__global__ void __launch_bounds__(256) attn_tc()
{
    __shared__ float qch[64][36], qcl[64][36];
    __shared__ float kvh[32][68], kvl[32][68];
    __shared__ float psh[32][36], psl[32][36];
    __shared__ float lsum[32];
    const int b = blockIdx.y;
    const int c0 = blockIdx.x * 32;
    const int tid = threadIdx.x;
    const int warp = tid >> 5, lane = tid & 31;
    const int grp = lane >> 2, tig = lane & 3;

    const int wms = (warp & 1) * 16;
    const int wnc = (warp >> 1) * 8;
    const int wmc = (warp & 1) * 16;
    const int wne = (warp >> 1) * 16;

    for (int i = tid; i < 32 * 16; i += 256) {
        const int c = i / 16, e4 = (i % 16) * 4;
        float4 v = *(const float4*)&g_qc[((size_t)(b * CC + c0 + c)) * 64 + e4];
        float h, l;
        split_tf32f(v.x, h, l); qch[e4 + 0][c] = h; qcl[e4 + 0][c] = l;
        split_tf32f(v.y, h, l); qch[e4 + 1][c] = h; qcl[e4 + 1][c] = l;
        split_tf32f(v.z, h, l); qch[e4 + 2][c] = h; qcl[e4 + 2][c] = l;
        split_tf32f(v.w, h, l); qch[e4 + 3][c] = h; qcl[e4 + 3][c] = l;
    }
    if (tid < 32) lsum[tid] = 0.f;

    float vacc[2][4];
#pragma unroll
    for (int tn = 0; tn < 2; tn++)
#pragma unroll
        for (int r = 0; r < 4; r++) vacc[tn][r] = 0.f;
    __syncthreads();

    for (int s0 = 0; s0 < LL; s0 += 32) {
        for (int i = tid; i < 32 * 16; i += 256) {
            const int s = i / 16, e4 = (i % 16) * 4;
            float4 v = *(const float4*)&g_k[((size_t)(b * LL + s0 + s)) * 64 + e4];
            float4 hv, lv;
            split_tf32f(v.x, hv.x, lv.x);
            split_tf32f(v.y, hv.y, lv.y);
            split_tf32f(v.z, hv.z, lv.z);
            split_tf32f(v.w, hv.w, lv.w);
            *(float4*)&kvh[s][e4] = hv;
            *(float4*)&kvl[s][e4] = lv;
        }
        __syncthreads();
        float sacc[4] = {0.f, 0.f, 0.f, 0.f};
#pragma unroll
        for (int k0 = 0; k0 < 64; k0 += 8) {
            float ah0 = kvh[wms + grp    ][k0 + tig    ];
            float ah1 = kvh[wms + grp + 8][k0 + tig    ];
            float ah2 = kvh[wms + grp    ][k0 + tig + 4];
            float ah3 = kvh[wms + grp + 8][k0 + tig + 4];
            float al0 = kvl[wms + grp    ][k0 + tig    ];
            float al1 = kvl[wms + grp + 8][k0 + tig    ];
            float al2 = kvl[wms + grp    ][k0 + tig + 4];
            float al3 = kvl[wms + grp + 8][k0 + tig + 4];
            float bh0 = qch[k0 + tig    ][wnc + grp];
            float bh1 = qch[k0 + tig + 4][wnc + grp];
            float bl0 = qcl[k0 + tig    ][wnc + grp];
            float bl1 = qcl[k0 + tig + 4][wnc + grp];
            mma_tf32f(sacc, ah0, ah1, ah2, ah3, bh0, bh1);
            mma_tf32f(sacc, ah0, ah1, ah2, ah3, bl0, bl1);
            mma_tf32f(sacc, al0, al1, al2, al3, bh0, bh1);
        }
#pragma unroll
        for (int r = 0; r < 2; r++)
#pragma unroll
            for (int j = 0; j < 2; j++) {
                const int srow = wms + grp + r * 8;
                const int ccol = wnc + tig * 2 + j;
                float ex = __expf(sacc[r * 2 + j] * TEMP_F);
                float h, l;
                split_tf32f(ex, h, l);
                psh[srow][ccol] = h;
                psl[srow][ccol] = l;
            }
        __syncthreads();
        for (int i = tid; i < 32 * 16; i += 256) {
            const int s = i / 16, e4 = (i % 16) * 4;
            float4 v = *(const float4*)&g_v[((size_t)(b * LL + s0 + s)) * 64 + e4];
            float4 hv, lv;
            split_tf32f(v.x, hv.x, lv.x);
            split_tf32f(v.y, hv.y, lv.y);
            split_tf32f(v.z, hv.z, lv.z);
            split_tf32f(v.w, hv.w, lv.w);
            *(float4*)&kvh[s][e4] = hv;
            *(float4*)&kvl[s][e4] = lv;
        }
        if (tid < 32) {
            float l = 0.f;
            for (int s = 0; s < 32; s++) l += psh[s][tid] + psl[s][tid];
            lsum[tid] += l;
        }
        __syncthreads();
#pragma unroll
        for (int k0 = 0; k0 < 32; k0 += 8) {
            float ah0 = psh[k0 + tig    ][wmc + grp    ];
            float ah1 = psh[k0 + tig    ][wmc + grp + 8];
            float ah2 = psh[k0 + tig + 4][wmc + grp    ];
            float ah3 = psh[k0 + tig + 4][wmc + grp + 8];
            float al0 = psl[k0 + tig    ][wmc + grp    ];
            float al1 = psl[k0 + tig    ][wmc + grp + 8];
            float al2 = psl[k0 + tig + 4][wmc + grp    ];
            float al3 = psl[k0 + tig + 4][wmc + grp + 8];
#pragma unroll
            for (int tn = 0; tn < 2; tn++) {
                const int n0 = wne + tn * 8 + grp;
                float bh0 = kvh[k0 + tig    ][n0];
                float bh1 = kvh[k0 + tig + 4][n0];
                float bl0 = kvl[k0 + tig    ][n0];
                float bl1 = kvl[k0 + tig + 4][n0];
                mma_tf32f(vacc[tn], ah0, ah1, ah2, ah3, bh0, bh1);
                mma_tf32f(vacc[tn], ah0, ah1, ah2, ah3, bl0, bl1);
                mma_tf32f(vacc[tn], al0, al1, al2, al3, bh0, bh1);
            }
        }
        __syncthreads();
    }
#pragma unroll
    for (int tn = 0; tn < 2; tn++)
#pragma unroll
        for (int r = 0; r < 2; r++) {
            const int cloc = wmc + grp + r * 8;
            const float inv = 1.f / lsum[cloc];
#pragma unroll
            for (int j = 0; j < 2; j++) {
                const int e = wne + tn * 8 + tig * 2 + j;
                g_vc[((size_t)(b * CC + c0 + cloc)) * 64 + e] = vacc[tn][r * 2 + j] * inv;
            }
        }
}

// ---------------- launch ----------------
extern "C" void kernel_launch(void* const* d_in, const int* in_sizes, int n_in,
                              void* d_out, int out_size)
{
    const float* x      = (const float*)d_in[0];
    const float* Wq     = (const float*)d_in[2];
    const float* bq     = (const float*)d_in[3];
    const float* Wk     = (const float*)d_in[4];
    const float* bk     = (const float*)d_in[5];
    const float* Wv     = (const float*)d_in[6];
    const float* bv     = (const float*)d_in[7];
    const float* Wo     = (const float*)d_in[8];
    const float* bo     = (const float*)d_in[9];
    const float* planes = (const float*)d_in[10];
    float* out = (float*)d_out;

    gemm_qkv_mixed<<<dim3(16, 256), 256>>>(x, Wq, bq, Wk, bk, Wv, bv);
    codes_kernel<<<2048, 256>>>(planes);                                // FROZEN
    km_init<<<64, 256>>>();
    for (int it = 0; it < KM_ITERS; it++) {
        km_assign<<<dim3(16, 64), 256>>>(0);
        km_update<<<64, 256>>>();
    }
    km_assign<<<dim3(16, 64), 256>>>(1);
    qc_kernel<<<dim3(4, 64), 256>>>();                                  // FROZEN
    attn_tc<<<dim3(8, 64), 256>>>();                                    // tensor-core attention
    gemm_out_g<<<dim3(8, 128), 256>>>(Wo, bo, out);
}